// round 3
// baseline (speedup 1.0000x reference)
#include <cuda_runtime.h>

// warp3D via shared-memory tiles.
// out[b,c,z,y,x] = trilinear gather of I at (x+fx, y+fy, z+fz).
// B=2, C=2, D=160, H=192, W=224, fp32.
//
// One block per 56x16x8 output tile. Stage channel-packed float2 tile
// (64x24x16 incl. halo, edge-replicated) in smem; gather via LDS instead of
// random L1tex gathers. Rare out-of-halo samples fall back to global loads.

#define Wd 224
#define Hd 192
#define Dd 160
#define HWd (Hd * Wd)            // 43008
#define DHWd (Dd * HWd)          // 6881280

#define TX 56
#define TY 16
#define TZ 8
#define HALO 3                   // lower halo; upper slack = 5
#define SX (TX + 8)              // 64
#define SY (TY + 8)              // 24
#define SZ (TZ + 8)              // 16
#define SMEM_SLOTS (SX * SY * SZ)     // 24576 float2 = 192 KB
#define TILE_VOX (TX * TY * TZ)       // 7168
#define NTHREADS 512

__global__ __launch_bounds__(NTHREADS) void warp3d_tile_kernel(
    const float* __restrict__ I,
    const float* __restrict__ flow,
    float* __restrict__ out)
{
    extern __shared__ float2 tile[];   // [SZ][SY][SX]

    const int tid = threadIdx.x;
    const int xs = blockIdx.x * TX;
    const int ys = blockIdx.y * TY;
    const int zcomb = blockIdx.z;             // 0..(D/TZ * B)-1
    const int zs = (zcomb % (Dd / TZ)) * TZ;
    const int b  = zcomb / (Dd / TZ);

    const int xlo = xs - HALO, ylo = ys - HALO, zlo = zs - HALO;

    const float* __restrict__ I0 = I + (long)b * 2 * DHWd;  // channel 0
    const float* __restrict__ I1 = I0 + DHWd;               // channel 1

    // ---- stage tile (coalesced; edge-replicated via clamp) ----
#pragma unroll 4
    for (int t = tid; t < SMEM_SLOTS; t += NTHREADS) {
        const int xp = t & (SX - 1);          // SX=64
        const int yp = (t >> 6) % SY;
        const int zp = t / (SX * SY);
        const int gx = min(max(xlo + xp, 0), Wd - 1);
        const int gy = min(max(ylo + yp, 0), Hd - 1);
        const int gz = min(max(zlo + zp, 0), Dd - 1);
        const long gi = (long)gz * HWd + gy * Wd + gx;
        float2 v;
        v.x = __ldg(I0 + gi);
        v.y = __ldg(I1 + gi);
        tile[t] = v;
    }
    __syncthreads();

    const float* __restrict__ fb = flow + (long)b * 3 * DHWd;
    float* __restrict__ ob = out + (long)b * 2 * DHWd;

    // ---- gather: 14 voxels per thread ----
#pragma unroll 2
    for (int v = tid; v < TILE_VOX; v += NTHREADS) {
        const int lx = v % TX;
        const int rem = v / TX;
        const int ly = rem % TY;
        const int lz = rem / TY;
        const int x = xs + lx, y = ys + ly, z = zs + lz;
        const long s = (long)z * HWd + y * Wd + x;

        const float fx = __ldg(fb + s);
        const float fy = __ldg(fb + s + DHWd);
        const float fz = __ldg(fb + s + 2L * DHWd);

        const float xf = fx + (float)x;
        const float yf = fy + (float)y;
        const float zf = fz + (float)z;

        int x0 = (int)floorf(xf);
        int y0 = (int)floorf(yf);
        int z0 = (int)floorf(zf);
        // Order matters: x1 from UNclamped x0+1, then clamp both (matches ref).
        const int x1 = min(max(x0 + 1, 0), Wd - 1);
        const int y1 = min(max(y0 + 1, 0), Hd - 1);
        const int z1 = min(max(z0 + 1, 0), Dd - 1);
        x0 = min(max(x0, 0), Wd - 1);
        y0 = min(max(y0, 0), Hd - 1);
        z0 = min(max(z0, 0), Dd - 1);

        // Weights from CLAMPED upper corner (matches reference).
        const float dx = (float)x1 - xf;
        const float dy = (float)y1 - yf;
        const float dz = (float)z1 - zf;
        const float ex = 1.0f - dx;
        const float ey = 1.0f - dy;
        const float ez = 1.0f - dz;

        const float w00 = dx * dy;   // (y0,x0)
        const float w10 = dx * ey;   // (y1,x0)
        const float w01 = ex * dy;   // (y0,x1)
        const float w11 = ex * ey;   // (y1,x1)

        float2 a0, a1, a2, a3, b0, b1, b2, b3;

        const bool in_tile =
            (x0 >= xlo) & (x1 <= xlo + SX - 1) &
            (y0 >= ylo) & (y1 <= ylo + SY - 1) &
            (z0 >= zlo) & (z1 <= zlo + SZ - 1);

        if (in_tile) {
            const int tx0 = x0 - xlo, tx1 = x1 - xlo;
            const int ry00 = ((z0 - zlo) * SY + (y0 - ylo)) * SX;
            const int ry10 = ((z0 - zlo) * SY + (y1 - ylo)) * SX;
            const int ry01 = ((z1 - zlo) * SY + (y0 - ylo)) * SX;
            const int ry11 = ((z1 - zlo) * SY + (y1 - ylo)) * SX;
            a0 = tile[ry00 + tx0];
            a1 = tile[ry10 + tx0];
            a2 = tile[ry00 + tx1];
            a3 = tile[ry10 + tx1];
            b0 = tile[ry01 + tx0];
            b1 = tile[ry11 + tx0];
            b2 = tile[ry01 + tx1];
            b3 = tile[ry11 + tx1];
        } else {
            // Rare fallback: direct global gather (original layout).
            const long g00 = (long)z0 * HWd + (long)y0 * Wd;
            const long g10 = (long)z0 * HWd + (long)y1 * Wd;
            const long g01 = (long)z1 * HWd + (long)y0 * Wd;
            const long g11 = (long)z1 * HWd + (long)y1 * Wd;
            a0.x = __ldg(I0 + g00 + x0); a0.y = __ldg(I1 + g00 + x0);
            a1.x = __ldg(I0 + g10 + x0); a1.y = __ldg(I1 + g10 + x0);
            a2.x = __ldg(I0 + g00 + x1); a2.y = __ldg(I1 + g00 + x1);
            a3.x = __ldg(I0 + g10 + x1); a3.y = __ldg(I1 + g10 + x1);
            b0.x = __ldg(I0 + g01 + x0); b0.y = __ldg(I1 + g01 + x0);
            b1.x = __ldg(I0 + g11 + x0); b1.y = __ldg(I1 + g11 + x0);
            b2.x = __ldg(I0 + g01 + x1); b2.y = __ldg(I1 + g01 + x1);
            b3.x = __ldg(I0 + g11 + x1); b3.y = __ldg(I1 + g11 + x1);
        }

        // z0-plane bilinear, both channels
        const float p0x = w00 * a0.x + w10 * a1.x + w01 * a2.x + w11 * a3.x;
        const float p0y = w00 * a0.y + w10 * a1.y + w01 * a2.y + w11 * a3.y;
        // z1-plane bilinear
        const float p1x = w00 * b0.x + w10 * b1.x + w01 * b2.x + w11 * b3.x;
        const float p1y = w00 * b0.y + w10 * b1.y + w01 * b2.y + w11 * b3.y;

        ob[s]        = dz * p0x + ez * p1x;
        ob[s + DHWd] = dz * p0y + ez * p1y;
    }
}

extern "C" void kernel_launch(void* const* d_in, const int* in_sizes, int n_in,
                              void* d_out, int out_size)
{
    const float* I    = (const float*)d_in[0];
    const float* flow = (const float*)d_in[1];
    float* out        = (float*)d_out;

    static bool configured = false;
    if (!configured) {
        cudaFuncSetAttribute(warp3d_tile_kernel,
                             cudaFuncAttributeMaxDynamicSharedMemorySize,
                             SMEM_SLOTS * sizeof(float2));
        configured = true;
    }

    dim3 block(NTHREADS, 1, 1);
    dim3 grid(Wd / TX, Hd / TY, (Dd / TZ) * 2);   // 4 x 12 x 40 = 1920 blocks
    warp3d_tile_kernel<<<grid, block, SMEM_SLOTS * sizeof(float2)>>>(I, flow, out);
}